// round 15
// baseline (speedup 1.0000x reference)
#include <cuda_runtime.h>
#include <cstdint>

// Shapes (fixed per reference): B=1024, C=200, L=3, DIM=512, SEQ=C+1=201
#define B_   1024
#define C_   200
#define DIM_ 512
#define SEQ_ 201
#define BT   8        // batch rows per block
#define SG   4        // seq positions per block (4 independent 64-thread groups)
#define GRX  ((SEQ_ + SG - 1) / SG)   // 51 (s>=201 guarded out)

// out[b,0,d]   = cls[d] + pe[0,d]
// out[b,c+1,d] = x[b,clamp(c-1)]*W[c,0,d] + x[b,c]*W[c,1,d] + x[b,clamp(c+1)]*W[c,2,d] + pe[c+1,d]

// 256-bit streaming store (sm_100+): one STG.256, evict-first in L2
__device__ __forceinline__ void stcs8(float* p, const float* v) {
    asm volatile("st.global.cs.v8.f32 [%0], {%1, %2, %3, %4, %5, %6, %7, %8};"
                 :: "l"(p), "f"(v[0]), "f"(v[1]), "f"(v[2]), "f"(v[3]),
                    "f"(v[4]), "f"(v[5]), "f"(v[6]), "f"(v[7]) : "memory");
}

__global__ __launch_bounds__(256, 4)
void GSE_band_proj_kernel(const float* __restrict__ x,
                          const float* __restrict__ W,
                          const float* __restrict__ cls,
                          const float* __restrict__ pe,
                          float* __restrict__ out) {
    __shared__ float xs[SG][3][BT];          // x windows for 4 s-groups (384 B)

    const int t      = threadIdx.x;
    const int g      = t >> 6;               // 0..3  (s-group)
    const int lane   = t & 63;               // 0..63 (owns 8 floats = 32 B of DIM)
    const int s      = blockIdx.x * SG + g;  // 0..203 (>=201 guarded)
    const int b_base = blockIdx.y * BT;
    const uint32_t doff = (uint32_t)lane * 8;

    // Cooperative x-window fill: xs[g][j][i] = x[b_base+i, clamp((bx*SG+g)-2+j)]
    if (t < SG * 3 * BT) {
        const int gg  = t / (3 * BT);
        const int rem = t % (3 * BT);
        const int j   = rem / BT;
        const int i   = rem % BT;
        int col = blockIdx.x * SG + gg - 2 + j;   // c-1+j for c = s-1
        col = (col < 0) ? 0 : (col > C_ - 1 ? C_ - 1 : col);
        xs[gg][j][i] = __ldg(x + (uint32_t)(b_base + i) * C_ + col);
    }
    __syncthreads();

    if (s >= SEQ_) return;

    if (s == 0) {
        // cls row: batch-invariant, pure store stream
        float r[8];
        {
            const float4 c0 = reinterpret_cast<const float4*>(cls)[lane * 2];
            const float4 c1 = reinterpret_cast<const float4*>(cls)[lane * 2 + 1];
            const float4 p0 = reinterpret_cast<const float4*>(pe)[lane * 2];
            const float4 p1 = reinterpret_cast<const float4*>(pe)[lane * 2 + 1];
            r[0] = c0.x + p0.x; r[1] = c0.y + p0.y; r[2] = c0.z + p0.z; r[3] = c0.w + p0.w;
            r[4] = c1.x + p1.x; r[5] = c1.y + p1.y; r[6] = c1.z + p1.z; r[7] = c1.w + p1.w;
        }
        uint32_t off = (uint32_t)b_base * (SEQ_ * DIM_) + doff;
        #pragma unroll
        for (int i = 0; i < BT; i++) {
            stcs8(out + off, r);
            off += SEQ_ * DIM_;
        }
        return;
    }

    const int c = s - 1;                     // 0..199

    // Per-(c,lane) constants: 8 floats per operand, reused across BT rows.
    float w0[8], w1[8], w2[8], pv[8];
    {
        const float4* Wr = reinterpret_cast<const float4*>(W + (uint32_t)c * 3 * DIM_) + lane * 2;
        const float4 a0 = Wr[0],               a1 = Wr[1];
        const float4 b0 = Wr[DIM_ / 4],        b1 = Wr[DIM_ / 4 + 1];
        const float4 c0 = Wr[DIM_ / 2],        c1 = Wr[DIM_ / 2 + 1];
        const float4 p0 = reinterpret_cast<const float4*>(pe + (uint32_t)(c + 1) * DIM_)[lane * 2];
        const float4 p1 = reinterpret_cast<const float4*>(pe + (uint32_t)(c + 1) * DIM_)[lane * 2 + 1];
        w0[0]=a0.x; w0[1]=a0.y; w0[2]=a0.z; w0[3]=a0.w; w0[4]=a1.x; w0[5]=a1.y; w0[6]=a1.z; w0[7]=a1.w;
        w1[0]=b0.x; w1[1]=b0.y; w1[2]=b0.z; w1[3]=b0.w; w1[4]=b1.x; w1[5]=b1.y; w1[6]=b1.z; w1[7]=b1.w;
        w2[0]=c0.x; w2[1]=c0.y; w2[2]=c0.z; w2[3]=c0.w; w2[4]=c1.x; w2[5]=c1.y; w2[6]=c1.z; w2[7]=c1.w;
        pv[0]=p0.x; pv[1]=p0.y; pv[2]=p0.z; pv[3]=p0.w; pv[4]=p1.x; pv[5]=p1.y; pv[6]=p1.z; pv[7]=p1.w;
    }

    uint32_t off = ((uint32_t)b_base * SEQ_ + (uint32_t)s) * DIM_ + doff;
    #pragma unroll
    for (int i = 0; i < BT; i++) {
        const float a = xs[g][0][i];         // broadcast LDS (group-uniform)
        const float m = xs[g][1][i];
        const float z = xs[g][2][i];
        float r[8];
        #pragma unroll
        for (int j = 0; j < 8; j++)
            r[j] = fmaf(a, w0[j], fmaf(m, w1[j], fmaf(z, w2[j], pv[j])));
        stcs8(out + off, r);
        off += SEQ_ * DIM_;
    }
}

extern "C" void kernel_launch(void* const* d_in, const int* in_sizes, int n_in,
                              void* d_out, int out_size) {
    const float* x   = (const float*)d_in[0];
    const float* W   = (const float*)d_in[1];
    const float* cls = (const float*)d_in[2];
    const float* pe  = (const float*)d_in[3];
    float* out = (float*)d_out;

    dim3 grid(GRX, B_ / BT, 1);    // 51 x 128 blocks = 6528 CTAs
    dim3 block(256, 1, 1);         // 4 independent 64-thread s-groups
    GSE_band_proj_kernel<<<grid, block>>>(x, W, cls, pe, out);
}

// round 16
// speedup vs baseline: 1.0344x; 1.0344x over previous
#include <cuda_runtime.h>
#include <cstdint>

// Shapes (fixed per reference): B=1024, C=200, L=3, DIM=512, SEQ=C+1=201
#define B_   1024
#define C_   200
#define DIM_ 512
#define SEQ_ 201
#define BT   8        // batch rows per block
#define SP   2        // seq positions per block (two independent 128-thread halves)
#define GRX  ((SEQ_ + SP - 1) / SP)   // 101 (s=201 guarded out)

// out[b,0,d]   = cls[d] + pe[0,d]
// out[b,c+1,d] = x[b,clamp(c-1)]*W[c,0,d] + x[b,c]*W[c,1,d] + x[b,clamp(c+1)]*W[c,2,d] + pe[c+1,d]
//
// Converged configuration (session evidence):
//  - .cs streaming stores: R1->R2 -12% (protects warm L2-resident x/W/pe)
//  - NS=1/BT=8/x-in-registers/no barrier: every structural alternative tied or regressed
//  - 2x128-thread independent halves: halves CTA count at zero coupling cost
//  - 32-bit addressing: regs 56->48, best cold profile (59.4us, DRAM 77.4%)
//  - falsified levers: occupancy (R12), STG.256 (R14), L2 write retention (R3),
//    deep tiling (R5/R9), grid-order swap (R10)
// Kernel sits at the HW pure-write drain ceiling (~7.0 TB/s effective).

__device__ __forceinline__ void stcs4(float4* p, float4 v) {
    // streaming store: evict-first in L2
    asm volatile("st.global.cs.v4.f32 [%0], {%1, %2, %3, %4};"
                 :: "l"(p), "f"(v.x), "f"(v.y), "f"(v.z), "f"(v.w) : "memory");
}

__global__ __launch_bounds__(256, 5)
void GSE_band_proj_kernel(const float* __restrict__ x,
                          const float* __restrict__ W,
                          const float* __restrict__ cls,
                          const float* __restrict__ pe,
                          float* __restrict__ out) {
    // Two fully independent 128-thread halves per CTA; no smem, no barrier.
    const int half = threadIdx.x >> 7;          // 0 or 1
    const int d4   = threadIdx.x & 127;         // 0..127 (float4 index into DIM)
    const int s    = blockIdx.x * SP + half;    // 0..201 (201 guarded)
    const int b_base = blockIdx.y * BT;

    if (s >= SEQ_) return;

    float4* const out4 = reinterpret_cast<float4*>(out);
    const uint32_t d4u = (uint32_t)d4;

    if (s == 0) {
        const float4 cv = reinterpret_cast<const float4*>(cls)[d4];
        const float4 pv = reinterpret_cast<const float4*>(pe)[d4];
        float4 r;
        r.x = cv.x + pv.x;
        r.y = cv.y + pv.y;
        r.z = cv.z + pv.z;
        r.w = cv.w + pv.w;
        uint32_t off = (uint32_t)b_base * (SEQ_ * DIM_ / 4) + d4u;
        #pragma unroll
        for (int i = 0; i < BT; i++) {
            stcs4(out4 + off, r);
            off += SEQ_ * DIM_ / 4;
        }
        return;
    }

    const int c   = s - 1;                       // 0..199
    const int cm1 = (c > 0)      ? c - 1 : 0;    // edge-replicate pad
    const int cp1 = (c < C_ - 1) ? c + 1 : C_ - 1;

    // Prefetch ALL x values for the 8 batch rows — fully independent LDGs;
    // the store loop never waits on a load.
    float xa[BT], xm[BT], xz[BT];
    {
        uint32_t row = (uint32_t)b_base * C_;
        #pragma unroll
        for (int i = 0; i < BT; i++) {
            xa[i] = __ldg(x + row + cm1);
            xm[i] = __ldg(x + row + c);
            xz[i] = __ldg(x + row + cp1);
            row += C_;
        }
    }

    // Per-(c,d4) constants, loaded once, reused across BT batch rows.
    const float4* W4 = reinterpret_cast<const float4*>(W);
    const uint32_t wbase = (uint32_t)c * (3 * DIM_ / 4) + d4u;
    const float4 w0 = W4[wbase];
    const float4 w1 = W4[wbase + DIM_ / 4];
    const float4 w2 = W4[wbase + 2 * (DIM_ / 4)];
    const float4 pv = reinterpret_cast<const float4*>(pe)[(uint32_t)(c + 1) * (DIM_ / 4) + d4u];

    uint32_t off = ((uint32_t)b_base * SEQ_ + (uint32_t)s) * (DIM_ / 4) + d4u;
    #pragma unroll
    for (int i = 0; i < BT; i++) {
        float4 r;
        r.x = fmaf(xa[i], w0.x, fmaf(xm[i], w1.x, fmaf(xz[i], w2.x, pv.x)));
        r.y = fmaf(xa[i], w0.y, fmaf(xm[i], w1.y, fmaf(xz[i], w2.y, pv.y)));
        r.z = fmaf(xa[i], w0.z, fmaf(xm[i], w1.z, fmaf(xz[i], w2.z, pv.z)));
        r.w = fmaf(xa[i], w0.w, fmaf(xm[i], w1.w, fmaf(xz[i], w2.w, pv.w)));
        stcs4(out4 + off, r);
        off += SEQ_ * DIM_ / 4;
    }
}

extern "C" void kernel_launch(void* const* d_in, const int* in_sizes, int n_in,
                              void* d_out, int out_size) {
    const float* x   = (const float*)d_in[0];
    const float* W   = (const float*)d_in[1];
    const float* cls = (const float*)d_in[2];
    const float* pe  = (const float*)d_in[3];
    float* out = (float*)d_out;

    dim3 grid(GRX, B_ / BT, 1);    // 101 x 128 blocks = 12928 CTAs
    dim3 block(256, 1, 1);         // two independent 128-thread halves
    GSE_band_proj_kernel<<<grid, block>>>(x, W, cls, pe, out);
}